// round 3
// baseline (speedup 1.0000x reference)
#include <cuda_runtime.h>

#define B_MAX 4096

// Scratch (device globals — allocation is forbidden). 16B-aligned for float4.
__device__ __align__(16) float g_w[B_MAX * 128];     // per-graph gate vector  w_b = Wk @ q_b
__device__ __align__(16) float g_c[B_MAX];           // per-graph gate bias    c_b = bk . q_b
__device__ __align__(16) float g_xagg[B_MAX * 128];  // gated segment sums

// ---------------------------------------------------------------------------
// Kernel 1: per-graph precompute. 32 graphs per block, 128 threads.
//   q_b = u_b @ Wq + bq   [64];  w_b = Wk @ q_b  [128];  c_b = bk . q_b
// Also zeroes g_xagg (scratch must be re-zeroed every replay).
// ---------------------------------------------------------------------------
__global__ void prep_kernel(const float* __restrict__ u,
                            const float* __restrict__ Wk,
                            const float* __restrict__ bk,
                            const float* __restrict__ Wq,
                            const float* __restrict__ bq,
                            int B) {
    __shared__ float su[32 * 128];
    __shared__ float sq[32 * 64];
    const int tid = threadIdx.x;
    const int g0  = blockIdx.x * 32;

    for (int i = tid; i < 32 * 128; i += 128) {
        int g = i >> 7, f = i & 127;
        su[i] = (g0 + g < B) ? u[(size_t)(g0 + g) * 128 + f] : 0.0f;
    }
    __syncthreads();

    // q = u @ Wq + bq   (lanes vary h -> coalesced Wq reads; su broadcast)
    for (int i = tid; i < 32 * 64; i += 128) {
        int g = i >> 6, h = i & 63;
        float s = bq[h];
        const float* ur = su + g * 128;
#pragma unroll 8
        for (int f = 0; f < 128; f++) s += ur[f] * Wq[f * 64 + h];
        sq[i] = s;
    }
    __syncthreads();

    // c = bk . q
    if (tid < 32 && g0 + tid < B) {
        float s = 0.0f;
        const float* qr = sq + tid * 64;
#pragma unroll 8
        for (int h = 0; h < 64; h++) s += bk[h] * qr[h];
        g_c[g0 + tid] = s;
    }

    // w = Wk @ q ; zero x_agg
    for (int i = tid; i < 32 * 128; i += 128) {
        int g = i >> 7, f = i & 127;
        if (g0 + g >= B) continue;
        float s = 0.0f;
        const float* qr = sq + g * 64;
#pragma unroll 8
        for (int h = 0; h < 64; h++) s += Wk[f * 64 + h] * qr[h];
        g_w[(size_t)(g0 + g) * 128 + f]    = s;
        g_xagg[(size_t)(g0 + g) * 128 + f] = 0.0f;
    }
}

// ---------------------------------------------------------------------------
// Kernel 2: HBM-bound streaming pass over x (512 MB). One warp per node.
// batch arrives as int32 (harness supports float32/int32/bf16 only).
// ---------------------------------------------------------------------------
__global__ void __launch_bounds__(256, 8)
main_kernel(const float* __restrict__ x,
            const int* __restrict__ batch,
            int N, int chunk) {
    const int warp = threadIdx.x >> 5;
    const int lane = threadIdx.x & 31;
    long start = (long)blockIdx.x * chunk;
    long end   = start + chunk;
    if (end > N) end = N;

    float4 acc = make_float4(0.f, 0.f, 0.f, 0.f);
    int cur = -1;

    for (long node = start + warp; node < end; node += 8) {
        // mask defensively: valid data in [0,B); if dtype guess were wrong this
        // turns a crash into a rel_err signal.
        const int b = batch[node] & (B_MAX - 1);
        const float4 xv = __ldg((const float4*)(x + (size_t)node * 128) + lane);
        const float4 wv = __ldg((const float4*)(g_w + (size_t)b * 128) + lane);

        float dot = xv.x * wv.x + xv.y * wv.y + xv.z * wv.z + xv.w * wv.w;
        dot += __shfl_xor_sync(0xffffffffu, dot, 16);
        dot += __shfl_xor_sync(0xffffffffu, dot, 8);
        dot += __shfl_xor_sync(0xffffffffu, dot, 4);
        dot += __shfl_xor_sync(0xffffffffu, dot, 2);
        dot += __shfl_xor_sync(0xffffffffu, dot, 1);

        const float a = 1.0f / (1.0f + __expf(-(dot + g_c[b])));

        if (b != cur) {
            if (cur >= 0) {
                float* p = g_xagg + (size_t)cur * 128 + lane * 4;
                atomicAdd(p + 0, acc.x);
                atomicAdd(p + 1, acc.y);
                atomicAdd(p + 2, acc.z);
                atomicAdd(p + 3, acc.w);
            }
            acc = make_float4(0.f, 0.f, 0.f, 0.f);
            cur = b;
        }
        acc.x += a * xv.x;
        acc.y += a * xv.y;
        acc.z += a * xv.z;
        acc.w += a * xv.w;
    }
    if (cur >= 0) {
        float* p = g_xagg + (size_t)cur * 128 + lane * 4;
        atomicAdd(p + 0, acc.x);
        atomicAdd(p + 1, acc.y);
        atomicAdd(p + 2, acc.z);
        atomicAdd(p + 3, acc.w);
    }
}

// ---------------------------------------------------------------------------
// Kernel 3: out = concat(x_agg, u) @ Wu + bu.   [B,256]@[256,128]
// ---------------------------------------------------------------------------
__global__ void final_kernel(const float* __restrict__ u,
                             const float* __restrict__ Wu,
                             const float* __restrict__ bu,
                             float* __restrict__ out,
                             int B) {
    __shared__ float s[16 * 256];
    const int j  = threadIdx.x;  // output column 0..127
    const int g0 = blockIdx.x * 16;

    for (int idx = threadIdx.x; idx < 16 * 256; idx += 128) {
        int g = idx >> 8, i = idx & 255;
        s[idx] = (g0 + g < B)
                   ? ((i < 128) ? g_xagg[(size_t)(g0 + g) * 128 + i]
                                : u[(size_t)(g0 + g) * 128 + (i - 128)])
                   : 0.0f;
    }
    __syncthreads();

    float acc[16];
    const float b0 = bu[j];
#pragma unroll
    for (int g = 0; g < 16; g++) acc[g] = b0;

    for (int i = 0; i < 256; i++) {
        const float wv = Wu[i * 128 + j];  // coalesced across threads
#pragma unroll
        for (int g = 0; g < 16; g++) acc[g] += s[g * 256 + i] * wv;  // smem broadcast
    }
#pragma unroll
    for (int g = 0; g < 16; g++)
        if (g0 + g < B) out[(size_t)(g0 + g) * 128 + j] = acc[g];
}

// ---------------------------------------------------------------------------
// Launch
// ---------------------------------------------------------------------------
extern "C" void kernel_launch(void* const* d_in, const int* in_sizes, int n_in,
                              void* d_out, int out_size) {
    const float* x     = (const float*)d_in[0];
    // d_in[1] = edge_index (unused), d_in[2] = e (unused)
    const float* u     = (const float*)d_in[3];
    const int*   batch = (const int*)d_in[4];   // int64 in reference -> int32 on device
    const float* Wk    = (const float*)d_in[5];
    const float* bk    = (const float*)d_in[6];
    const float* Wq    = (const float*)d_in[7];
    const float* bq    = (const float*)d_in[8];
    const float* Wu    = (const float*)d_in[9];
    const float* bu    = (const float*)d_in[10];
    float* out = (float*)d_out;

    const int N = in_sizes[0] / 128;   // 1,000,000
    const int B = out_size / 128;      // 4096

    prep_kernel<<<(B + 31) / 32, 128>>>(u, Wk, bk, Wq, bq, B);

    const int chunk = 2048;
    const int grid  = (N + chunk - 1) / chunk;
    main_kernel<<<grid, 256>>>(x, batch, N, chunk);

    final_kernel<<<(B + 15) / 16, 128>>>(u, Wu, bu, out, B);
}

// round 4
// speedup vs baseline: 2.6837x; 2.6837x over previous
#include <cuda_runtime.h>

#define B_MAX 4096
#define GPB   16     // graphs per prep block

// Scratch (device globals — allocation is forbidden). 16B-aligned for float4.
__device__ __align__(16) float g_w[B_MAX * 128];     // per-graph gate vector  w_b = Wk @ q_b
__device__ __align__(16) float g_c[B_MAX];           // per-graph gate bias    c_b = bk . q_b
__device__ __align__(16) float g_xagg[B_MAX * 128];  // gated segment sums

// ---------------------------------------------------------------------------
// Kernel 1: per-graph precompute. 16 graphs/block, 256 threads, 256 blocks.
//   q_b = u_b @ Wq + bq ; w_b = Wk @ q_b ; c_b = bk . q_b ; zero g_xagg.
// Register-tiled; Wk staged via padded transposed smem (conflict-free LDS).
// ---------------------------------------------------------------------------
__global__ void __launch_bounds__(256)
prep_kernel(const float* __restrict__ u,
            const float* __restrict__ Wk,
            const float* __restrict__ bk,
            const float* __restrict__ Wq,
            const float* __restrict__ bq,
            int B) {
    __shared__ float su[GPB * 128];        // 8 KB
    __shared__ float sq[GPB * 64];         // 4 KB
    __shared__ float sWkT[64 * 129];       // ~33 KB, [h][f] padded

    const int tid = threadIdx.x;
    const int g0  = blockIdx.x * GPB;

    // load 16 u rows (float4-vectorized, coalesced)
    for (int i = tid; i < GPB * 32; i += 256) {
        int g = i >> 5, c = i & 31;
        ((float4*)su)[i] = ((const float4*)(u + (size_t)(g0 + g) * 128))[c];
    }
    // stage Wk transposed: read Wk[f*64+h] coalesced, write sWkT[h*129+f]
    for (int i = tid; i < 128 * 64; i += 256) {
        int f = i >> 6, h = i & 63;
        sWkT[h * 129 + f] = Wk[i];
    }
    __syncthreads();

    // q phase: thread = (gq, h); gq owns graphs gq*4..gq*4+3
    {
        const int h = tid & 63, gq = tid >> 6;
        const float* s0 = su + (gq * 4 + 0) * 128;
        const float* s1 = su + (gq * 4 + 1) * 128;
        const float* s2 = su + (gq * 4 + 2) * 128;
        const float* s3 = su + (gq * 4 + 3) * 128;
        float a0 = bq[h], a1 = a0, a2 = a0, a3 = a0;
#pragma unroll 4
        for (int f = 0; f < 128; f++) {
            const float wq = Wq[f * 64 + h];   // coalesced across lanes (h)
            a0 += s0[f] * wq;                  // smem broadcast
            a1 += s1[f] * wq;
            a2 += s2[f] * wq;
            a3 += s3[f] * wq;
        }
        sq[(gq * 4 + 0) * 64 + h] = a0;
        sq[(gq * 4 + 1) * 64 + h] = a1;
        sq[(gq * 4 + 2) * 64 + h] = a2;
        sq[(gq * 4 + 3) * 64 + h] = a3;
    }
    __syncthreads();

    // c phase
    if (tid < GPB && g0 + tid < B) {
        float s = 0.0f;
        const float* qr = sq + tid * 64;
#pragma unroll 8
        for (int h = 0; h < 64; h++) s += bk[h] * qr[h];
        g_c[g0 + tid] = s;
    }

    // w phase: thread = (q8, f); q8 owns graphs q8*8..q8*8+7
    {
        const int f = tid & 127, q8 = tid >> 7;
        float acc[8];
#pragma unroll
        for (int j = 0; j < 8; j++) acc[j] = 0.0f;
#pragma unroll 4
        for (int h = 0; h < 64; h++) {
            const float wk = sWkT[h * 129 + f];  // lanes vary f -> conflict-free
#pragma unroll
            for (int j = 0; j < 8; j++) acc[j] += sq[(q8 * 8 + j) * 64 + h] * wk;
        }
#pragma unroll
        for (int j = 0; j < 8; j++) {
            const int g = g0 + q8 * 8 + j;
            if (g < B) {
                g_w[(size_t)g * 128 + f]    = acc[j];
                g_xagg[(size_t)g * 128 + f] = 0.0f;
            }
        }
    }
}

// ---------------------------------------------------------------------------
// Kernel 2: HBM-bound streaming pass over x (512 MB). One warp per node,
// unrolled x4 for MLP (8 independent 128B LDGs in flight per warp iter).
// ---------------------------------------------------------------------------
__device__ __forceinline__ float warp_sum(float d) {
    d += __shfl_xor_sync(0xffffffffu, d, 16);
    d += __shfl_xor_sync(0xffffffffu, d, 8);
    d += __shfl_xor_sync(0xffffffffu, d, 4);
    d += __shfl_xor_sync(0xffffffffu, d, 2);
    d += __shfl_xor_sync(0xffffffffu, d, 1);
    return d;
}

__global__ void __launch_bounds__(256)
main_kernel(const float* __restrict__ x,
            const int* __restrict__ batch,
            int N, int chunk) {
    const int warp = threadIdx.x >> 5;
    const int lane = threadIdx.x & 31;
    long start = (long)blockIdx.x * chunk;
    long end   = start + chunk;
    if (end > N) end = N;

    float4 acc = make_float4(0.f, 0.f, 0.f, 0.f);
    int cur = -1;

    long node = start + warp;
    const long lim4 = end - 24;

    for (; node < lim4; node += 32) {
        const int b0 = batch[node]      & (B_MAX - 1);
        const int b1 = batch[node + 8]  & (B_MAX - 1);
        const int b2 = batch[node + 16] & (B_MAX - 1);
        const int b3 = batch[node + 24] & (B_MAX - 1);

        const float4 x0 = __ldcs((const float4*)(x + (size_t)(node)      * 128) + lane);
        const float4 x1 = __ldcs((const float4*)(x + (size_t)(node + 8)  * 128) + lane);
        const float4 x2 = __ldcs((const float4*)(x + (size_t)(node + 16) * 128) + lane);
        const float4 x3 = __ldcs((const float4*)(x + (size_t)(node + 24) * 128) + lane);
        const float4 w0 = __ldg((const float4*)(g_w + (size_t)b0 * 128) + lane);
        const float4 w1 = __ldg((const float4*)(g_w + (size_t)b1 * 128) + lane);
        const float4 w2 = __ldg((const float4*)(g_w + (size_t)b2 * 128) + lane);
        const float4 w3 = __ldg((const float4*)(g_w + (size_t)b3 * 128) + lane);

        float d0 = x0.x * w0.x + x0.y * w0.y + x0.z * w0.z + x0.w * w0.w;
        float d1 = x1.x * w1.x + x1.y * w1.y + x1.z * w1.z + x1.w * w1.w;
        float d2 = x2.x * w2.x + x2.y * w2.y + x2.z * w2.z + x2.w * w2.w;
        float d3 = x3.x * w3.x + x3.y * w3.y + x3.z * w3.z + x3.w * w3.w;
        d0 = warp_sum(d0); d1 = warp_sum(d1); d2 = warp_sum(d2); d3 = warp_sum(d3);

        const float a0 = 1.0f / (1.0f + __expf(-(d0 + g_c[b0])));
        const float a1 = 1.0f / (1.0f + __expf(-(d1 + g_c[b1])));
        const float a2 = 1.0f / (1.0f + __expf(-(d2 + g_c[b2])));
        const float a3 = 1.0f / (1.0f + __expf(-(d3 + g_c[b3])));

#define ACCUM(bi, ai, xi)                                               \
        if (bi != cur) {                                                \
            if (cur >= 0) {                                             \
                float* p = g_xagg + (size_t)cur * 128 + lane * 4;       \
                atomicAdd(p + 0, acc.x); atomicAdd(p + 1, acc.y);       \
                atomicAdd(p + 2, acc.z); atomicAdd(p + 3, acc.w);       \
            }                                                           \
            acc = make_float4(0.f, 0.f, 0.f, 0.f);                      \
            cur = bi;                                                   \
        }                                                               \
        acc.x += ai * xi.x; acc.y += ai * xi.y;                         \
        acc.z += ai * xi.z; acc.w += ai * xi.w;

        ACCUM(b0, a0, x0)
        ACCUM(b1, a1, x1)
        ACCUM(b2, a2, x2)
        ACCUM(b3, a3, x3)
    }

    // scalar tail
    for (; node < end; node += 8) {
        const int b = batch[node] & (B_MAX - 1);
        const float4 xv = __ldcs((const float4*)(x + (size_t)node * 128) + lane);
        const float4 wv = __ldg((const float4*)(g_w + (size_t)b * 128) + lane);
        float d = xv.x * wv.x + xv.y * wv.y + xv.z * wv.z + xv.w * wv.w;
        d = warp_sum(d);
        const float a = 1.0f / (1.0f + __expf(-(d + g_c[b])));
        ACCUM(b, a, xv)
    }
#undef ACCUM

    if (cur >= 0) {
        float* p = g_xagg + (size_t)cur * 128 + lane * 4;
        atomicAdd(p + 0, acc.x); atomicAdd(p + 1, acc.y);
        atomicAdd(p + 2, acc.z); atomicAdd(p + 3, acc.w);
    }
}

// ---------------------------------------------------------------------------
// Kernel 3: out = concat(x_agg, u) @ Wu + bu.   [B,256]@[256,128]
// ---------------------------------------------------------------------------
__global__ void __launch_bounds__(128)
final_kernel(const float* __restrict__ u,
             const float* __restrict__ Wu,
             const float* __restrict__ bu,
             float* __restrict__ out,
             int B) {
    __shared__ float s[16 * 256];
    const int j  = threadIdx.x;  // output column 0..127
    const int g0 = blockIdx.x * 16;

    for (int idx = threadIdx.x; idx < 16 * 256; idx += 128) {
        int g = idx >> 8, i = idx & 255;
        s[idx] = (g0 + g < B)
                   ? ((i < 128) ? g_xagg[(size_t)(g0 + g) * 128 + i]
                                : u[(size_t)(g0 + g) * 128 + (i - 128)])
                   : 0.0f;
    }
    __syncthreads();

    float acc[16];
    const float b0 = bu[j];
#pragma unroll
    for (int g = 0; g < 16; g++) acc[g] = b0;

    for (int i = 0; i < 256; i++) {
        const float wv = Wu[i * 128 + j];  // coalesced across threads
#pragma unroll
        for (int g = 0; g < 16; g++) acc[g] += s[g * 256 + i] * wv;  // smem broadcast
    }
#pragma unroll
    for (int g = 0; g < 16; g++)
        if (g0 + g < B) out[(size_t)(g0 + g) * 128 + j] = acc[g];
}

// ---------------------------------------------------------------------------
// Launch
// ---------------------------------------------------------------------------
extern "C" void kernel_launch(void* const* d_in, const int* in_sizes, int n_in,
                              void* d_out, int out_size) {
    const float* x     = (const float*)d_in[0];
    // d_in[1] = edge_index (unused), d_in[2] = e (unused)
    const float* u     = (const float*)d_in[3];
    const int*   batch = (const int*)d_in[4];   // int64 in reference -> int32 on device
    const float* Wk    = (const float*)d_in[5];
    const float* bk    = (const float*)d_in[6];
    const float* Wq    = (const float*)d_in[7];
    const float* bq    = (const float*)d_in[8];
    const float* Wu    = (const float*)d_in[9];
    const float* bu    = (const float*)d_in[10];
    float* out = (float*)d_out;

    const int N = in_sizes[0] / 128;   // 1,000,000
    const int B = out_size / 128;      // 4096

    prep_kernel<<<(B + GPB - 1) / GPB, 256>>>(u, Wk, bk, Wq, bq, B);

    const int chunk = 1024;
    const int grid  = (N + chunk - 1) / chunk;
    main_kernel<<<grid, 256>>>(x, batch, N, chunk);

    final_kernel<<<(B + 15) / 16, 128>>>(u, Wu, bu, out, B);
}

// round 5
// speedup vs baseline: 2.9256x; 1.0901x over previous
#include <cuda_runtime.h>

#define B_MAX 4096
#define GPB   16     // graphs per prep block

// Scratch (device globals — allocation is forbidden). 16B-aligned for float4.
__device__ __align__(16) float g_w[B_MAX * 128];     // per-graph gate vector  w_b = Wk @ q_b
__device__ __align__(16) float g_c[B_MAX];           // per-graph gate bias    c_b = bk . q_b
__device__ __align__(16) float g_xagg[B_MAX * 128];  // gated segment sums
__device__ __align__(16) float g_wkT[64 * 128];      // Wk transposed [h][f]

// ---------------------------------------------------------------------------
// Kernel 0: transpose Wk (128x64 -> 64x128). One block, trivial.
// ---------------------------------------------------------------------------
__global__ void transpose_wk(const float* __restrict__ Wk) {
    for (int i = threadIdx.x; i < 128 * 64; i += blockDim.x) {
        int f = i >> 6, h = i & 63;
        g_wkT[h * 128 + f] = Wk[i];
    }
}

// ---------------------------------------------------------------------------
// Kernel 1: per-graph precompute. 16 graphs/block, 256 threads, 256 blocks.
//   q_b = u_b @ Wq + bq ; w_b = WkT^T... ; c_b = bk . q_b ; zero g_xagg.
// Only 12 KB smem -> high occupancy; WkT read coalesced from L2.
// ---------------------------------------------------------------------------
__global__ void __launch_bounds__(256)
prep_kernel(const float* __restrict__ u,
            const float* __restrict__ bk,
            const float* __restrict__ Wq,
            const float* __restrict__ bq,
            int B) {
    __shared__ float su[GPB * 128];        // 8 KB
    __shared__ float sq[GPB * 64];         // 4 KB

    const int tid = threadIdx.x;
    const int g0  = blockIdx.x * GPB;

    // load 16 u rows (float4-vectorized, coalesced)
    for (int i = tid; i < GPB * 32; i += 256) {
        int g = i >> 5, c = i & 31;
        ((float4*)su)[i] = ((const float4*)(u + (size_t)(g0 + g) * 128))[c];
    }
    __syncthreads();

    // q phase: thread = (gq, h); gq owns graphs gq*4..gq*4+3
    {
        const int h = tid & 63, gq = tid >> 6;
        const float* s0 = su + (gq * 4 + 0) * 128;
        const float* s1 = su + (gq * 4 + 1) * 128;
        const float* s2 = su + (gq * 4 + 2) * 128;
        const float* s3 = su + (gq * 4 + 3) * 128;
        float a0 = bq[h], a1 = a0, a2 = a0, a3 = a0;
#pragma unroll 4
        for (int f = 0; f < 128; f++) {
            const float wq = Wq[f * 64 + h];   // coalesced across lanes (h)
            a0 += s0[f] * wq;                  // smem broadcast
            a1 += s1[f] * wq;
            a2 += s2[f] * wq;
            a3 += s3[f] * wq;
        }
        sq[(gq * 4 + 0) * 64 + h] = a0;
        sq[(gq * 4 + 1) * 64 + h] = a1;
        sq[(gq * 4 + 2) * 64 + h] = a2;
        sq[(gq * 4 + 3) * 64 + h] = a3;
    }
    __syncthreads();

    // c phase
    if (tid < GPB && g0 + tid < B) {
        float s = 0.0f;
        const float* qr = sq + tid * 64;
#pragma unroll 8
        for (int h = 0; h < 64; h++) s += bk[h] * qr[h];
        g_c[g0 + tid] = s;
    }

    // w phase: thread = (q8, f); q8 owns graphs q8*8..q8*8+7.
    // g_wkT[h*128+f]: lanes vary f -> coalesced, L2-resident (32 KB).
    {
        const int f = tid & 127, q8 = tid >> 7;
        float acc[8];
#pragma unroll
        for (int j = 0; j < 8; j++) acc[j] = 0.0f;
#pragma unroll 4
        for (int h = 0; h < 64; h++) {
            const float wk = g_wkT[h * 128 + f];
#pragma unroll
            for (int j = 0; j < 8; j++) acc[j] += sq[(q8 * 8 + j) * 64 + h] * wk;
        }
#pragma unroll
        for (int j = 0; j < 8; j++) {
            const int g = g0 + q8 * 8 + j;
            if (g < B) {
                g_w[(size_t)g * 128 + f]    = acc[j];
                g_xagg[(size_t)g * 128 + f] = 0.0f;
            }
        }
    }
}

// ---------------------------------------------------------------------------
// Kernel 2: HBM-bound streaming pass over x (512 MB). One warp per node,
// unrolled x4 for MLP. w-vector + bias CACHED IN REGISTERS across the sorted
// segment (avg length ~244) -> g_w L2 traffic drops from 512 MB to ~2 MB.
// ---------------------------------------------------------------------------
__device__ __forceinline__ float warp_sum(float d) {
    d += __shfl_xor_sync(0xffffffffu, d, 16);
    d += __shfl_xor_sync(0xffffffffu, d, 8);
    d += __shfl_xor_sync(0xffffffffu, d, 4);
    d += __shfl_xor_sync(0xffffffffu, d, 2);
    d += __shfl_xor_sync(0xffffffffu, d, 1);
    return d;
}

__global__ void __launch_bounds__(256)
main_kernel(const float* __restrict__ x,
            const int* __restrict__ batch,
            int N, int chunk) {
    const int warp = threadIdx.x >> 5;
    const int lane = threadIdx.x & 31;
    long start = (long)blockIdx.x * chunk;
    long end   = start + chunk;
    if (end > N) end = N;

    float4 acc = make_float4(0.f, 0.f, 0.f, 0.f);
    float4 wv  = make_float4(0.f, 0.f, 0.f, 0.f);
    float  cb  = 0.0f;
    int    cur = -1;

    long node = start + warp;
    const long lim4 = end - 24;

#define PROC(bi, xi)                                                    \
        if (bi != cur) {                                                \
            if (cur >= 0) {                                             \
                float* p = g_xagg + (size_t)cur * 128 + lane * 4;       \
                atomicAdd(p + 0, acc.x); atomicAdd(p + 1, acc.y);       \
                atomicAdd(p + 2, acc.z); atomicAdd(p + 3, acc.w);       \
            }                                                           \
            acc = make_float4(0.f, 0.f, 0.f, 0.f);                      \
            cur = bi;                                                   \
            wv  = __ldg((const float4*)(g_w + (size_t)bi * 128) + lane);\
            cb  = g_c[bi];                                              \
        }                                                               \
        {                                                               \
            float d = xi.x * wv.x + xi.y * wv.y + xi.z * wv.z + xi.w * wv.w; \
            d = warp_sum(d);                                            \
            const float a = 1.0f / (1.0f + __expf(-(d + cb)));          \
            acc.x += a * xi.x; acc.y += a * xi.y;                       \
            acc.z += a * xi.z; acc.w += a * xi.w;                       \
        }

    for (; node < lim4; node += 32) {
        const int b0 = batch[node]      & (B_MAX - 1);
        const int b1 = batch[node + 8]  & (B_MAX - 1);
        const int b2 = batch[node + 16] & (B_MAX - 1);
        const int b3 = batch[node + 24] & (B_MAX - 1);

        const float4 x0 = __ldcs((const float4*)(x + (size_t)(node)      * 128) + lane);
        const float4 x1 = __ldcs((const float4*)(x + (size_t)(node + 8)  * 128) + lane);
        const float4 x2 = __ldcs((const float4*)(x + (size_t)(node + 16) * 128) + lane);
        const float4 x3 = __ldcs((const float4*)(x + (size_t)(node + 24) * 128) + lane);

        PROC(b0, x0)
        PROC(b1, x1)
        PROC(b2, x2)
        PROC(b3, x3)
    }

    // scalar tail
    for (; node < end; node += 8) {
        const int b = batch[node] & (B_MAX - 1);
        const float4 xv = __ldcs((const float4*)(x + (size_t)node * 128) + lane);
        PROC(b, xv)
    }
#undef PROC

    if (cur >= 0) {
        float* p = g_xagg + (size_t)cur * 128 + lane * 4;
        atomicAdd(p + 0, acc.x); atomicAdd(p + 1, acc.y);
        atomicAdd(p + 2, acc.z); atomicAdd(p + 3, acc.w);
    }
}

// ---------------------------------------------------------------------------
// Kernel 3: out = concat(x_agg, u) @ Wu + bu.   [B,256]@[256,128]
// ---------------------------------------------------------------------------
__global__ void __launch_bounds__(128)
final_kernel(const float* __restrict__ u,
             const float* __restrict__ Wu,
             const float* __restrict__ bu,
             float* __restrict__ out,
             int B) {
    __shared__ float s[16 * 256];
    const int j  = threadIdx.x;  // output column 0..127
    const int g0 = blockIdx.x * 16;

    for (int idx = threadIdx.x; idx < 16 * 256; idx += 128) {
        int g = idx >> 8, i = idx & 255;
        s[idx] = (g0 + g < B)
                   ? ((i < 128) ? g_xagg[(size_t)(g0 + g) * 128 + i]
                                : u[(size_t)(g0 + g) * 128 + (i - 128)])
                   : 0.0f;
    }
    __syncthreads();

    float acc[16];
    const float b0 = bu[j];
#pragma unroll
    for (int g = 0; g < 16; g++) acc[g] = b0;

    for (int i = 0; i < 256; i++) {
        const float wv = Wu[i * 128 + j];  // coalesced across threads
#pragma unroll
        for (int g = 0; g < 16; g++) acc[g] += s[g * 256 + i] * wv;  // smem broadcast
    }
#pragma unroll
    for (int g = 0; g < 16; g++)
        if (g0 + g < B) out[(size_t)(g0 + g) * 128 + j] = acc[g];
}

// ---------------------------------------------------------------------------
// Launch
// ---------------------------------------------------------------------------
extern "C" void kernel_launch(void* const* d_in, const int* in_sizes, int n_in,
                              void* d_out, int out_size) {
    const float* x     = (const float*)d_in[0];
    // d_in[1] = edge_index (unused), d_in[2] = e (unused)
    const float* u     = (const float*)d_in[3];
    const int*   batch = (const int*)d_in[4];   // int64 in reference -> int32 on device
    const float* Wk    = (const float*)d_in[5];
    const float* bk    = (const float*)d_in[6];
    const float* Wq    = (const float*)d_in[7];
    const float* bq    = (const float*)d_in[8];
    const float* Wu    = (const float*)d_in[9];
    const float* bu    = (const float*)d_in[10];
    float* out = (float*)d_out;

    const int N = in_sizes[0] / 128;   // 1,000,000
    const int B = out_size / 128;      // 4096

    transpose_wk<<<1, 256>>>(Wk);
    prep_kernel<<<(B + GPB - 1) / GPB, 256>>>(u, bk, Wq, bq, B);

    const int chunk = 1024;
    const int grid  = (N + chunk - 1) / chunk;
    main_kernel<<<grid, 256>>>(x, batch, N, chunk);

    final_kernel<<<(B + 15) / 16, 128>>>(u, Wu, bu, out, B);
}

// round 6
// speedup vs baseline: 3.3669x; 1.1508x over previous
#include <cuda_runtime.h>

#define B_MAX 4096
#define GPB   16     // graphs per prep block

// Scratch (device globals — allocation is forbidden). 16B-aligned for float4.
__device__ __align__(16) float g_w[B_MAX * 128];     // per-graph gate vector  w_b = Wk @ q_b
__device__ __align__(16) float g_c[B_MAX];           // per-graph gate bias    c_b = bk . q_b
__device__ __align__(16) float g_xagg[B_MAX * 128];  // gated segment sums
__device__ __align__(16) float g_wkT[64 * 128];      // Wk transposed [h][f]

// ---------------------------------------------------------------------------
// Kernel 0: transpose Wk (128x64 -> 64x128).
// ---------------------------------------------------------------------------
__global__ void transpose_wk(const float* __restrict__ Wk) {
    int i = blockIdx.x * 256 + threadIdx.x;
    if (i < 128 * 64) {
        int f = i >> 6, h = i & 63;
        g_wkT[h * 128 + f] = Wk[i];
    }
}

// ---------------------------------------------------------------------------
// Kernel 1: per-graph precompute. 16 graphs/block, 256 threads, 256 blocks.
//   q_b = u_b @ Wq + bq ; w_b = Wk @ q_b ; c_b = bk . q_b ; zero g_xagg.
// ---------------------------------------------------------------------------
__global__ void __launch_bounds__(256)
prep_kernel(const float* __restrict__ u,
            const float* __restrict__ bk,
            const float* __restrict__ Wq,
            const float* __restrict__ bq,
            int B) {
    __shared__ float su[GPB * 128];        // 8 KB
    __shared__ float sq[GPB * 64];         // 4 KB

    const int tid = threadIdx.x;
    const int g0  = blockIdx.x * GPB;

    for (int i = tid; i < GPB * 32; i += 256) {
        int g = i >> 5, c = i & 31;
        ((float4*)su)[i] = ((const float4*)(u + (size_t)(g0 + g) * 128))[c];
    }
    __syncthreads();

    // q phase: thread = (gq, h); gq owns graphs gq*4..gq*4+3
    {
        const int h = tid & 63, gq = tid >> 6;
        const float* s0 = su + (gq * 4 + 0) * 128;
        const float* s1 = su + (gq * 4 + 1) * 128;
        const float* s2 = su + (gq * 4 + 2) * 128;
        const float* s3 = su + (gq * 4 + 3) * 128;
        float a0 = bq[h], a1 = a0, a2 = a0, a3 = a0;
#pragma unroll 4
        for (int f = 0; f < 128; f++) {
            const float wq = Wq[f * 64 + h];   // coalesced across lanes (h)
            a0 += s0[f] * wq;                  // smem broadcast
            a1 += s1[f] * wq;
            a2 += s2[f] * wq;
            a3 += s3[f] * wq;
        }
        sq[(gq * 4 + 0) * 64 + h] = a0;
        sq[(gq * 4 + 1) * 64 + h] = a1;
        sq[(gq * 4 + 2) * 64 + h] = a2;
        sq[(gq * 4 + 3) * 64 + h] = a3;
    }
    __syncthreads();

    // c phase
    if (tid < GPB && g0 + tid < B) {
        float s = 0.0f;
        const float* qr = sq + tid * 64;
#pragma unroll 8
        for (int h = 0; h < 64; h++) s += bk[h] * qr[h];
        g_c[g0 + tid] = s;
    }

    // w phase: thread = (q8, f); q8 owns graphs q8*8..q8*8+7.
    {
        const int f = tid & 127, q8 = tid >> 7;
        float acc[8];
#pragma unroll
        for (int j = 0; j < 8; j++) acc[j] = 0.0f;
#pragma unroll 4
        for (int h = 0; h < 64; h++) {
            const float wk = g_wkT[h * 128 + f];   // coalesced, L2-resident
#pragma unroll
            for (int j = 0; j < 8; j++) acc[j] += sq[(q8 * 8 + j) * 64 + h] * wk;
        }
#pragma unroll
        for (int j = 0; j < 8; j++) {
            const int g = g0 + q8 * 8 + j;
            if (g < B) {
                g_w[(size_t)g * 128 + f]    = acc[j];
                g_xagg[(size_t)g * 128 + f] = 0.0f;
            }
        }
    }
}

// ---------------------------------------------------------------------------
// Kernel 2: HBM-bound streaming pass over x (512 MB). One warp per node,
// unrolled x4 for MLP; w-vector + bias cached in registers across the sorted
// segment.
// ---------------------------------------------------------------------------
__device__ __forceinline__ float warp_sum(float d) {
    d += __shfl_xor_sync(0xffffffffu, d, 16);
    d += __shfl_xor_sync(0xffffffffu, d, 8);
    d += __shfl_xor_sync(0xffffffffu, d, 4);
    d += __shfl_xor_sync(0xffffffffu, d, 2);
    d += __shfl_xor_sync(0xffffffffu, d, 1);
    return d;
}

__global__ void __launch_bounds__(256)
main_kernel(const float* __restrict__ x,
            const int* __restrict__ batch,
            int N, int chunk) {
    const int warp = threadIdx.x >> 5;
    const int lane = threadIdx.x & 31;
    long start = (long)blockIdx.x * chunk;
    long end   = start + chunk;
    if (end > N) end = N;

    float4 acc = make_float4(0.f, 0.f, 0.f, 0.f);
    float4 wv  = make_float4(0.f, 0.f, 0.f, 0.f);
    float  cb  = 0.0f;
    int    cur = -1;

    long node = start + warp;
    const long lim4 = end - 24;

#define PROC(bi, xi)                                                    \
        if (bi != cur) {                                                \
            if (cur >= 0) {                                             \
                float* p = g_xagg + (size_t)cur * 128 + lane * 4;       \
                atomicAdd(p + 0, acc.x); atomicAdd(p + 1, acc.y);       \
                atomicAdd(p + 2, acc.z); atomicAdd(p + 3, acc.w);       \
            }                                                           \
            acc = make_float4(0.f, 0.f, 0.f, 0.f);                      \
            cur = bi;                                                   \
            wv  = __ldg((const float4*)(g_w + (size_t)bi * 128) + lane);\
            cb  = g_c[bi];                                              \
        }                                                               \
        {                                                               \
            float d = xi.x * wv.x + xi.y * wv.y + xi.z * wv.z + xi.w * wv.w; \
            d = warp_sum(d);                                            \
            const float a = 1.0f / (1.0f + __expf(-(d + cb)));          \
            acc.x += a * xi.x; acc.y += a * xi.y;                       \
            acc.z += a * xi.z; acc.w += a * xi.w;                       \
        }

    for (; node < lim4; node += 32) {
        const int b0 = batch[node]      & (B_MAX - 1);
        const int b1 = batch[node + 8]  & (B_MAX - 1);
        const int b2 = batch[node + 16] & (B_MAX - 1);
        const int b3 = batch[node + 24] & (B_MAX - 1);

        const float4 x0 = __ldcs((const float4*)(x + (size_t)(node)      * 128) + lane);
        const float4 x1 = __ldcs((const float4*)(x + (size_t)(node + 8)  * 128) + lane);
        const float4 x2 = __ldcs((const float4*)(x + (size_t)(node + 16) * 128) + lane);
        const float4 x3 = __ldcs((const float4*)(x + (size_t)(node + 24) * 128) + lane);

        PROC(b0, x0)
        PROC(b1, x1)
        PROC(b2, x2)
        PROC(b3, x3)
    }

    for (; node < end; node += 8) {
        const int b = batch[node] & (B_MAX - 1);
        const float4 xv = __ldcs((const float4*)(x + (size_t)node * 128) + lane);
        PROC(b, xv)
    }
#undef PROC

    if (cur >= 0) {
        float* p = g_xagg + (size_t)cur * 128 + lane * 4;
        atomicAdd(p + 0, acc.x); atomicAdd(p + 1, acc.y);
        atomicAdd(p + 2, acc.z); atomicAdd(p + 3, acc.w);
    }
}

// ---------------------------------------------------------------------------
// Kernel 3: out = concat(x_agg, u) @ Wu + bu.   [B,256]@[256,128]
// 256 threads: (half, j). half owns 128 of the 256 K-values (split-K x2,
// halves the serial load chain). Unroll x8 with batched independent Wu loads
// (MLP 8 hides the L2 latency that dominated the previous version).
// ---------------------------------------------------------------------------
__global__ void __launch_bounds__(256)
final_kernel(const float* __restrict__ u,
             const float* __restrict__ Wu,
             const float* __restrict__ bu,
             float* __restrict__ out,
             int B) {
    __shared__ float s[16 * 256];       // 16 KB concat inputs
    __shared__ float spart[16 * 128];   // 8 KB partials from half 1
    const int j    = threadIdx.x & 127;  // output column
    const int half = threadIdx.x >> 7;
    const int g0   = blockIdx.x * 16;

    // stage concat(x_agg, u) rows, float4-vectorized
    for (int idx = threadIdx.x; idx < 16 * 64; idx += 256) {
        int g = idx >> 6, c = idx & 63;   // c: float4 index within 256-float row
        float4 v;
        if (g0 + g < B)
            v = (c < 32) ? ((const float4*)(g_xagg + (size_t)(g0 + g) * 128))[c]
                         : ((const float4*)(u      + (size_t)(g0 + g) * 128))[c - 32];
        else
            v = make_float4(0.f, 0.f, 0.f, 0.f);
        ((float4*)s)[g * 64 + c] = v;
    }
    __syncthreads();

    float acc[16];
#pragma unroll
    for (int g = 0; g < 16; g++) acc[g] = 0.0f;

    const int i0 = half * 128;
    for (int ii = 0; ii < 128; ii += 8) {
        float wv[8];
#pragma unroll
        for (int t = 0; t < 8; t++)            // 8 independent coalesced LDGs
            wv[t] = Wu[(size_t)(i0 + ii + t) * 128 + j];
#pragma unroll
        for (int t = 0; t < 8; t++) {
            const int i = i0 + ii + t;
#pragma unroll
            for (int g = 0; g < 16; g++) acc[g] += s[g * 256 + i] * wv[t];
        }
    }

    if (half == 1) {
#pragma unroll
        for (int g = 0; g < 16; g++) spart[g * 128 + j] = acc[g];
    }
    __syncthreads();
    if (half == 0) {
        const float b0 = bu[j];
#pragma unroll
        for (int g = 0; g < 16; g++)
            if (g0 + g < B)
                out[(size_t)(g0 + g) * 128 + j] = acc[g] + spart[g * 128 + j] + b0;
    }
}

// ---------------------------------------------------------------------------
// Launch
// ---------------------------------------------------------------------------
extern "C" void kernel_launch(void* const* d_in, const int* in_sizes, int n_in,
                              void* d_out, int out_size) {
    const float* x     = (const float*)d_in[0];
    // d_in[1] = edge_index (unused), d_in[2] = e (unused)
    const float* u     = (const float*)d_in[3];
    const int*   batch = (const int*)d_in[4];   // int64 in reference -> int32 on device
    const float* Wk    = (const float*)d_in[5];
    const float* bk    = (const float*)d_in[6];
    const float* Wq    = (const float*)d_in[7];
    const float* bq    = (const float*)d_in[8];
    const float* Wu    = (const float*)d_in[9];
    const float* bu    = (const float*)d_in[10];
    float* out = (float*)d_out;

    const int N = in_sizes[0] / 128;   // 1,000,000
    const int B = out_size / 128;      // 4096

    transpose_wk<<<32, 256>>>(Wk);
    prep_kernel<<<(B + GPB - 1) / GPB, 256>>>(u, bk, Wq, bq, B);

    const int chunk = 1024;
    const int grid  = (N + chunk - 1) / chunk;
    main_kernel<<<grid, 256>>>(x, batch, N, chunk);

    final_kernel<<<(B + 15) / 16, 256>>>(u, Wu, bu, out, B);
}

// round 7
// speedup vs baseline: 3.4375x; 1.0210x over previous
#include <cuda_runtime.h>

#define B_MAX 4096
#define GPB   16     // graphs per prep block
#define GPF   8      // graphs per final block

// Scratch (device globals — allocation is forbidden). 16B-aligned for float4.
__device__ __align__(16) float g_w[B_MAX * 128];     // per-graph gate vector  w_b = Wk @ q_b
__device__ __align__(16) float g_c[B_MAX];           // per-graph gate bias    c_b = bk . q_b
__device__ __align__(16) float g_xagg[B_MAX * 128];  // gated segment sums
__device__ __align__(16) float g_wkT[64 * 128];      // Wk transposed [h][f]

// ---------------------------------------------------------------------------
// Kernel 0: transpose Wk (128x64 -> 64x128).
// ---------------------------------------------------------------------------
__global__ void transpose_wk(const float* __restrict__ Wk) {
    int i = blockIdx.x * 256 + threadIdx.x;
    if (i < 128 * 64) {
        int f = i >> 6, h = i & 63;
        g_wkT[h * 128 + f] = Wk[i];
    }
}

// ---------------------------------------------------------------------------
// Kernel 1: per-graph precompute. 16 graphs/block, 256 threads, 256 blocks.
//   q_b = u_b @ Wq + bq ; w_b = Wk @ q_b ; c_b = bk . q_b ; zero g_xagg.
// ---------------------------------------------------------------------------
__global__ void __launch_bounds__(256)
prep_kernel(const float* __restrict__ u,
            const float* __restrict__ bk,
            const float* __restrict__ Wq,
            const float* __restrict__ bq,
            int B) {
    __shared__ float su[GPB * 128];        // 8 KB
    __shared__ float sq[GPB * 64];         // 4 KB

    const int tid = threadIdx.x;
    const int g0  = blockIdx.x * GPB;

    for (int i = tid; i < GPB * 32; i += 256) {
        int g = i >> 5, c = i & 31;
        ((float4*)su)[i] = ((const float4*)(u + (size_t)(g0 + g) * 128))[c];
    }
    __syncthreads();

    // q phase: thread = (gq, h); gq owns graphs gq*4..gq*4+3.
    // Batched 8-wide Wq loads -> MLP 8 against L2 latency.
    {
        const int h = tid & 63, gq = tid >> 6;
        const float* s0 = su + (gq * 4 + 0) * 128;
        const float* s1 = su + (gq * 4 + 1) * 128;
        const float* s2 = su + (gq * 4 + 2) * 128;
        const float* s3 = su + (gq * 4 + 3) * 128;
        float a0 = bq[h], a1 = a0, a2 = a0, a3 = a0;
        for (int ff = 0; ff < 128; ff += 8) {
            float wq[8];
#pragma unroll
            for (int t = 0; t < 8; t++) wq[t] = Wq[(ff + t) * 64 + h];  // 8 independent LDGs
#pragma unroll
            for (int t = 0; t < 8; t++) {
                a0 += s0[ff + t] * wq[t];
                a1 += s1[ff + t] * wq[t];
                a2 += s2[ff + t] * wq[t];
                a3 += s3[ff + t] * wq[t];
            }
        }
        sq[(gq * 4 + 0) * 64 + h] = a0;
        sq[(gq * 4 + 1) * 64 + h] = a1;
        sq[(gq * 4 + 2) * 64 + h] = a2;
        sq[(gq * 4 + 3) * 64 + h] = a3;
    }
    __syncthreads();

    // c phase
    if (tid < GPB && g0 + tid < B) {
        float s = 0.0f;
        const float* qr = sq + tid * 64;
#pragma unroll 8
        for (int h = 0; h < 64; h++) s += bk[h] * qr[h];
        g_c[g0 + tid] = s;
    }

    // w phase: thread = (q8, f); q8 owns graphs q8*8..q8*8+7.
    {
        const int f = tid & 127, q8 = tid >> 7;
        float acc[8];
#pragma unroll
        for (int j = 0; j < 8; j++) acc[j] = 0.0f;
        for (int hh = 0; hh < 64; hh += 8) {
            float wk[8];
#pragma unroll
            for (int t = 0; t < 8; t++) wk[t] = g_wkT[(hh + t) * 128 + f];  // batched
#pragma unroll
            for (int t = 0; t < 8; t++) {
#pragma unroll
                for (int j = 0; j < 8; j++)
                    acc[j] += sq[(q8 * 8 + j) * 64 + hh + t] * wk[t];
            }
        }
#pragma unroll
        for (int j = 0; j < 8; j++) {
            const int g = g0 + q8 * 8 + j;
            if (g < B) {
                g_w[(size_t)g * 128 + f]    = acc[j];
                g_xagg[(size_t)g * 128 + f] = 0.0f;
            }
        }
    }
}

// ---------------------------------------------------------------------------
// Kernel 2: HBM-bound streaming pass over x (512 MB). One warp per node,
// unrolled x4 for MLP; w-vector + bias cached in registers across the sorted
// segment. At its HBM roofline.
// ---------------------------------------------------------------------------
__device__ __forceinline__ float warp_sum(float d) {
    d += __shfl_xor_sync(0xffffffffu, d, 16);
    d += __shfl_xor_sync(0xffffffffu, d, 8);
    d += __shfl_xor_sync(0xffffffffu, d, 4);
    d += __shfl_xor_sync(0xffffffffu, d, 2);
    d += __shfl_xor_sync(0xffffffffu, d, 1);
    return d;
}

__global__ void __launch_bounds__(256)
main_kernel(const float* __restrict__ x,
            const int* __restrict__ batch,
            int N, int chunk) {
    const int warp = threadIdx.x >> 5;
    const int lane = threadIdx.x & 31;
    long start = (long)blockIdx.x * chunk;
    long end   = start + chunk;
    if (end > N) end = N;

    float4 acc = make_float4(0.f, 0.f, 0.f, 0.f);
    float4 wv  = make_float4(0.f, 0.f, 0.f, 0.f);
    float  cb  = 0.0f;
    int    cur = -1;

    long node = start + warp;
    const long lim4 = end - 24;

#define PROC(bi, xi)                                                    \
        if (bi != cur) {                                                \
            if (cur >= 0) {                                             \
                float* p = g_xagg + (size_t)cur * 128 + lane * 4;       \
                atomicAdd(p + 0, acc.x); atomicAdd(p + 1, acc.y);       \
                atomicAdd(p + 2, acc.z); atomicAdd(p + 3, acc.w);       \
            }                                                           \
            acc = make_float4(0.f, 0.f, 0.f, 0.f);                      \
            cur = bi;                                                   \
            wv  = __ldg((const float4*)(g_w + (size_t)bi * 128) + lane);\
            cb  = g_c[bi];                                              \
        }                                                               \
        {                                                               \
            float d = xi.x * wv.x + xi.y * wv.y + xi.z * wv.z + xi.w * wv.w; \
            d = warp_sum(d);                                            \
            const float a = 1.0f / (1.0f + __expf(-(d + cb)));          \
            acc.x += a * xi.x; acc.y += a * xi.y;                       \
            acc.z += a * xi.z; acc.w += a * xi.w;                       \
        }

    for (; node < lim4; node += 32) {
        const int b0 = batch[node]      & (B_MAX - 1);
        const int b1 = batch[node + 8]  & (B_MAX - 1);
        const int b2 = batch[node + 16] & (B_MAX - 1);
        const int b3 = batch[node + 24] & (B_MAX - 1);

        const float4 x0 = __ldcs((const float4*)(x + (size_t)(node)      * 128) + lane);
        const float4 x1 = __ldcs((const float4*)(x + (size_t)(node + 8)  * 128) + lane);
        const float4 x2 = __ldcs((const float4*)(x + (size_t)(node + 16) * 128) + lane);
        const float4 x3 = __ldcs((const float4*)(x + (size_t)(node + 24) * 128) + lane);

        PROC(b0, x0)
        PROC(b1, x1)
        PROC(b2, x2)
        PROC(b3, x3)
    }

    for (; node < end; node += 8) {
        const int b = batch[node] & (B_MAX - 1);
        const float4 xv = __ldcs((const float4*)(x + (size_t)node * 128) + lane);
        PROC(b, xv)
    }
#undef PROC

    if (cur >= 0) {
        float* p = g_xagg + (size_t)cur * 128 + lane * 4;
        atomicAdd(p + 0, acc.x); atomicAdd(p + 1, acc.y);
        atomicAdd(p + 2, acc.z); atomicAdd(p + 3, acc.w);
    }
}

// ---------------------------------------------------------------------------
// Kernel 3: out = concat(x_agg, u) @ Wu + bu.   [B,256]@[256,128]
// 8 graphs/block -> 512 blocks (2x grid vs R5), split-K x2, 256 threads.
// acc[8] halves register pressure; batched-8 Wu loads hide L2 latency.
// ---------------------------------------------------------------------------
__global__ void __launch_bounds__(256)
final_kernel(const float* __restrict__ u,
             const float* __restrict__ Wu,
             const float* __restrict__ bu,
             float* __restrict__ out,
             int B) {
    __shared__ float s[GPF * 256];       // 8 KB concat inputs
    __shared__ float spart[GPF * 128];   // 4 KB partials from half 1
    const int j    = threadIdx.x & 127;  // output column
    const int half = threadIdx.x >> 7;
    const int g0   = blockIdx.x * GPF;

    // stage concat(x_agg, u) rows, float4-vectorized
    for (int idx = threadIdx.x; idx < GPF * 64; idx += 256) {
        int g = idx >> 6, c = idx & 63;   // c: float4 index within 256-float row
        float4 v;
        if (g0 + g < B)
            v = (c < 32) ? ((const float4*)(g_xagg + (size_t)(g0 + g) * 128))[c]
                         : ((const float4*)(u      + (size_t)(g0 + g) * 128))[c - 32];
        else
            v = make_float4(0.f, 0.f, 0.f, 0.f);
        ((float4*)s)[g * 64 + c] = v;
    }
    __syncthreads();

    float acc[GPF];
#pragma unroll
    for (int g = 0; g < GPF; g++) acc[g] = 0.0f;

    const int i0 = half * 128;
    for (int ii = 0; ii < 128; ii += 8) {
        float wv[8];
#pragma unroll
        for (int t = 0; t < 8; t++)            // 8 independent coalesced LDGs
            wv[t] = Wu[(size_t)(i0 + ii + t) * 128 + j];
#pragma unroll
        for (int t = 0; t < 8; t++) {
            const int i = i0 + ii + t;
#pragma unroll
            for (int g = 0; g < GPF; g++) acc[g] += s[g * 256 + i] * wv[t];
        }
    }

    if (half == 1) {
#pragma unroll
        for (int g = 0; g < GPF; g++) spart[g * 128 + j] = acc[g];
    }
    __syncthreads();
    if (half == 0) {
        const float b0 = bu[j];
#pragma unroll
        for (int g = 0; g < GPF; g++)
            if (g0 + g < B)
                out[(size_t)(g0 + g) * 128 + j] = acc[g] + spart[g * 128 + j] + b0;
    }
}

// ---------------------------------------------------------------------------
// Launch
// ---------------------------------------------------------------------------
extern "C" void kernel_launch(void* const* d_in, const int* in_sizes, int n_in,
                              void* d_out, int out_size) {
    const float* x     = (const float*)d_in[0];
    // d_in[1] = edge_index (unused), d_in[2] = e (unused)
    const float* u     = (const float*)d_in[3];
    const int*   batch = (const int*)d_in[4];   // int64 in reference -> int32 on device
    const float* Wk    = (const float*)d_in[5];
    const float* bk    = (const float*)d_in[6];
    const float* Wq    = (const float*)d_in[7];
    const float* bq    = (const float*)d_in[8];
    const float* Wu    = (const float*)d_in[9];
    const float* bu    = (const float*)d_in[10];
    float* out = (float*)d_out;

    const int N = in_sizes[0] / 128;   // 1,000,000
    const int B = out_size / 128;      // 4096

    transpose_wk<<<32, 256>>>(Wk);
    prep_kernel<<<(B + GPB - 1) / GPB, 256>>>(u, bk, Wq, bq, B);

    const int chunk = 1024;
    const int grid  = (N + chunk - 1) / chunk;
    main_kernel<<<grid, 256>>>(x, batch, N, chunk);

    final_kernel<<<(B + GPF - 1) / GPF, 256>>>(u, Wu, bu, out, B);
}